// round 5
// baseline (speedup 1.0000x reference)
#include <cuda_runtime.h>
#include <cstdint>

#define NN 100000
#define EE 1600000
#define ND 64
#define ED 8
#define HD 128
#define MSGIN 138
#define LDA 130          // padded leading dim for transposed A tiles (2-way conflicts only)

// Scratch: per-node message aggregation buffer (zeroed every launch)
__device__ float g_aggr[(size_t)NN * HD];

// ---------------- helpers ----------------

__device__ __forceinline__ float silu_f(float v) {
    return v / (1.0f + __expf(-v));
}

__device__ __forceinline__ unsigned long long pk2(float lo, float hi) {
    unsigned long long r;
    asm("mov.b64 %0, {%1, %2};" : "=l"(r) : "f"(lo), "f"(hi));
    return r;
}
__device__ __forceinline__ float2 up2(unsigned long long v) {
    float2 r;
    asm("mov.b64 {%0, %1}, %2;" : "=f"(r.x), "=f"(r.y) : "l"(v));
    return r;
}
// packed dual-FMA: d.lo += a.lo*b.lo ; d.hi += a.hi*b.hi   (Blackwell FFMA2)
__device__ __forceinline__ void f2fma(unsigned long long& d, unsigned long long a, unsigned long long b) {
    asm("fma.rn.f32x2 %0, %1, %2, %0;" : "+l"(d) : "l"(a), "l"(b));
}

// 128xK (A^T in SMEM, LDA=130) x Kx128 (B in SMEM, LD=128) -> 128x128 tile.
// Thread (ty,tx): rows ty*8..+7, col pairs {i*32+tx*2, +1} for i=0..3.
__device__ __forceinline__ void gemm128(const float* __restrict__ As_,
                                        const float* __restrict__ Bs_,
                                        const float* __restrict__ bias,
                                        int K, int ty, int tx,
                                        unsigned long long acc[8][4]) {
    const int c0 = tx * 2;
#pragma unroll
    for (int i = 0; i < 4; i++) {
        unsigned long long bi = pk2(bias[i * 32 + c0], bias[i * 32 + c0 + 1]);
#pragma unroll
        for (int j = 0; j < 8; j++) acc[j][i] = bi;
    }
    const float* ap = As_ + ty * 8;
    const float* bp = Bs_ + c0;
#pragma unroll 2
    for (int k = 0; k < K; k++) {
        float2 aA = *(const float2*)(ap + k * LDA + 0);
        float2 aB = *(const float2*)(ap + k * LDA + 2);
        float2 aC = *(const float2*)(ap + k * LDA + 4);
        float2 aD = *(const float2*)(ap + k * LDA + 6);
        unsigned long long a2[8];
        a2[0] = pk2(aA.x, aA.x); a2[1] = pk2(aA.y, aA.y);
        a2[2] = pk2(aB.x, aB.x); a2[3] = pk2(aB.y, aB.y);
        a2[4] = pk2(aC.x, aC.x); a2[5] = pk2(aC.y, aC.y);
        a2[6] = pk2(aD.x, aD.x); a2[7] = pk2(aD.y, aD.y);
        unsigned long long b0 = *(const unsigned long long*)(bp + k * 128 + 0);
        unsigned long long b1 = *(const unsigned long long*)(bp + k * 128 + 32);
        unsigned long long b2 = *(const unsigned long long*)(bp + k * 128 + 64);
        unsigned long long b3 = *(const unsigned long long*)(bp + k * 128 + 96);
#pragma unroll
        for (int j = 0; j < 8; j++) {
            f2fma(acc[j][0], a2[j], b0);
            f2fma(acc[j][1], a2[j], b1);
            f2fma(acc[j][2], a2[j], b2);
            f2fma(acc[j][3], a2[j], b3);
        }
    }
}

// silu each acc element in place
__device__ __forceinline__ void silu_acc(unsigned long long acc[8][4]) {
#pragma unroll
    for (int j = 0; j < 8; j++)
#pragma unroll
        for (int i = 0; i < 4; i++) {
            float2 t = up2(acc[j][i]);
            acc[j][i] = pk2(silu_f(t.x), silu_f(t.y));
        }
}

// write acc (optionally silu'd) transposed into As[c*LDA + r]
__device__ __forceinline__ void store_T(float* As_, unsigned long long acc[8][4],
                                        int ty, int tx, bool do_silu) {
#pragma unroll
    for (int j = 0; j < 8; j++) {
        int r = ty * 8 + j;
#pragma unroll
        for (int i = 0; i < 4; i++) {
            float2 t = up2(acc[j][i]);
            int c = i * 32 + tx * 2;
            As_[(c + 0) * LDA + r] = do_silu ? silu_f(t.x) : t.x;
            As_[(c + 1) * LDA + r] = do_silu ? silu_f(t.y) : t.y;
        }
    }
}

// silu(T) . wvec per row, half-warp reduce, then scatter 3 atomics per edge
__device__ __forceinline__ void dot_reduce_scatter(unsigned long long acc[8][4],
                                                   const float* __restrict__ wv,
                                                   float bscal,
                                                   const float* __restrict__ srel,
                                                   const float* __restrict__ ssq,
                                                   const int* __restrict__ srow,
                                                   float* __restrict__ outp,
                                                   int ty, int tx) {
    float s[8];
#pragma unroll
    for (int j = 0; j < 8; j++) {
        float acc_s = 0.f;
#pragma unroll
        for (int i = 0; i < 4; i++) {
            float2 t = up2(acc[j][i]);
            int c = i * 32 + tx * 2;
            acc_s += silu_f(t.x) * wv[c] + silu_f(t.y) * wv[c + 1];
        }
        s[j] = acc_s;
    }
#pragma unroll
    for (int o = 8; o > 0; o >>= 1) {
#pragma unroll
        for (int j = 0; j < 8; j++) s[j] += __shfl_xor_sync(0xffffffffu, s[j], o);
    }
    if (tx == 0) {
#pragma unroll
        for (int j = 0; j < 8; j++) {
            int r = ty * 8 + j;
            float w = (s[j] + bscal) / (ssq[r] + 1e-8f);
            int rw = srow[r];
            float* o = outp + (size_t)rw * 3;
            atomicAdd(o + 0, srel[r * 3 + 0] * w);
            atomicAdd(o + 1, srel[r * 3 + 1] * w);
            atomicAdd(o + 2, srel[r * 3 + 2] * w);
        }
    }
}

// ---------------- init kernel ----------------

__global__ void init_kernel(const float* __restrict__ x, const float* __restrict__ v,
                            float* __restrict__ out) {
    int idx = blockIdx.x * blockDim.x + threadIdx.x;
    int stride = gridDim.x * blockDim.x;
    for (int k = idx; k < NN * HD; k += stride) g_aggr[k] = 0.f;
    for (int k = idx; k < NN * 3; k += stride) {
        out[(size_t)NN * ND + k] = x[k];                 // x_new seed
        out[(size_t)NN * ND + (size_t)NN * 3 + k] = v[k]; // v_new seed
    }
}

// ---------------- edge kernel ----------------
// SMEM floats: As 138*130=17940, Bs 138*128=17664, srel 384, ssq 128, wc2 128, wv2 128, srow/scol 256 ints
#define EDGE_SMEM_FLOATS (17940 + 17664 + 384 + 128 + 128 + 128 + 256)
#define EDGE_SMEM_BYTES  (EDGE_SMEM_FLOATS * 4)

__global__ void __launch_bounds__(256, 1)
edge_kernel(const float* __restrict__ h, const float* __restrict__ x,
            const int* __restrict__ ei, const float* __restrict__ ea,
            const float* __restrict__ Wm1, const float* __restrict__ bm1,
            const float* __restrict__ Wm2, const float* __restrict__ bm2,
            const float* __restrict__ Wc1, const float* __restrict__ bc1,
            const float* __restrict__ Wc2, const float* __restrict__ bc2,
            const float* __restrict__ Wv1, const float* __restrict__ bv1,
            const float* __restrict__ Wv2, const float* __restrict__ bv2,
            float* __restrict__ outx, float* __restrict__ outv) {
    extern __shared__ float sm[];
    float* As   = sm;                   // 17940
    float* Bs   = As + 17940;           // 17664
    float* srel = Bs + 17664;           // 384
    float* ssq  = srel + 384;           // 128
    float* swc2 = ssq + 128;            // 128
    float* swv2 = swc2 + 128;           // 128
    int*   srow = (int*)(swv2 + 128);   // 128
    int*   scol = srow + 128;           // 128

    const int tid = threadIdx.x;
    const int tx = tid & 15;
    const int ty = tid >> 4;
    const int e0 = blockIdx.x * 128;

    // ---- phase 0: edge metadata (edge_index is int32: JAX default x64-disabled) ----
    if (tid < 128) {
        int e = e0 + tid;
        int r = ei[e];
        int c = ei[EE + e];
        srow[tid] = r; scol[tid] = c;
        float dx = x[r * 3 + 0] - x[c * 3 + 0];
        float dy = x[r * 3 + 1] - x[c * 3 + 1];
        float dz = x[r * 3 + 2] - x[c * 3 + 2];
        srel[tid * 3 + 0] = dx; srel[tid * 3 + 1] = dy; srel[tid * 3 + 2] = dz;
        float sq = dx * dx + dy * dy + dz * dz;
        ssq[tid] = sq;
        As[128 * LDA + tid] = sq;   // feature 128: squared_dist
        As[129 * LDA + tid] = dz;   // feature 129: z_diff
        swc2[tid] = Wc2[tid];
        swv2[tid] = Wv2[tid];
    }
    __syncthreads();

    // ---- phase 1: gather msg_in^T into As ----
    {
        int el = tid >> 1, part = tid & 1;
        const float4* hr = (const float4*)h + (size_t)srow[el] * 16 + part * 8;
        const float4* hc = (const float4*)h + (size_t)scol[el] * 16 + part * 8;
#pragma unroll
        for (int q = 0; q < 8; q++) {
            float4 f = hr[q];
            int k0 = part * 32 + q * 4;
            As[(k0 + 0) * LDA + el] = f.x; As[(k0 + 1) * LDA + el] = f.y;
            As[(k0 + 2) * LDA + el] = f.z; As[(k0 + 3) * LDA + el] = f.w;
        }
#pragma unroll
        for (int q = 0; q < 8; q++) {
            float4 f = hc[q];
            int k0 = 64 + part * 32 + q * 4;
            As[(k0 + 0) * LDA + el] = f.x; As[(k0 + 1) * LDA + el] = f.y;
            As[(k0 + 2) * LDA + el] = f.z; As[(k0 + 3) * LDA + el] = f.w;
        }
#pragma unroll
        for (int it = 0; it < 4; it++) {
            int idx = tid + it * 256;          // 1024 = 128 edges * 8 attrs
            int e = idx >> 3, j = idx & 7;
            As[(130 + j) * LDA + e] = ea[(size_t)e0 * 8 + idx];
        }
    }
    // Bs <- Wm1
    for (int i4 = tid; i4 < (MSGIN * 128) / 4; i4 += 256)
        ((float4*)Bs)[i4] = ((const float4*)Wm1)[i4];
    __syncthreads();

    unsigned long long acc[8][4];

    // ---- GEMM1: msg_in @ Wm1 + bm1 ----
    gemm128(As, Bs, bm1, MSGIN, ty, tx, acc);
    __syncthreads();
    store_T(As, acc, ty, tx, true);   // silu, transposed
    for (int i4 = tid; i4 < (128 * 128) / 4; i4 += 256)
        ((float4*)Bs)[i4] = ((const float4*)Wm2)[i4];
    __syncthreads();

    // ---- GEMM2: -> msg ----
    gemm128(As, Bs, bm2, 128, ty, tx, acc);
    silu_acc(acc);                    // acc = msg

    // msg aggregation: coalesced atomics (half-warp spans 128B)
#pragma unroll
    for (int j = 0; j < 8; j++) {
        int r = ty * 8 + j;
        float* dst = g_aggr + (size_t)srow[r] * HD + tx * 2;
#pragma unroll
        for (int i = 0; i < 4; i++) {
            float2 m = up2(acc[j][i]);
            atomicAdd(dst + i * 32 + 0, m.x);
            atomicAdd(dst + i * 32 + 1, m.y);
        }
    }
    __syncthreads();
    store_T(As, acc, ty, tx, false);  // msg^T (already silu'd)
    for (int i4 = tid; i4 < (128 * 128) / 4; i4 += 256)
        ((float4*)Bs)[i4] = ((const float4*)Wc1)[i4];
    __syncthreads();

    // ---- GEMM3: coordinate weights ----
    gemm128(As, Bs, bc1, 128, ty, tx, acc);
    dot_reduce_scatter(acc, swc2, bc2[0], srel, ssq, srow, outx, ty, tx);
    __syncthreads();
    for (int i4 = tid; i4 < (128 * 128) / 4; i4 += 256)
        ((float4*)Bs)[i4] = ((const float4*)Wv1)[i4];
    __syncthreads();

    // ---- GEMM4: velocity weights ----
    gemm128(As, Bs, bv1, 128, ty, tx, acc);
    dot_reduce_scatter(acc, swv2, bv2[0], srel, ssq, srow, outv, ty, tx);
}

// ---------------- node kernel ----------------
// SMEM: As 192*130 = 24960, Bs 192*128 = 24576
#define NODE_SMEM_FLOATS (24960 + 24576)
#define NODE_SMEM_BYTES  (NODE_SMEM_FLOATS * 4)

__global__ void __launch_bounds__(256, 1)
node_kernel(const float* __restrict__ h,
            const float* __restrict__ Wn1, const float* __restrict__ bn1,
            const float* __restrict__ Wn2, const float* __restrict__ bn2,
            float* __restrict__ out) {
    extern __shared__ float sm[];
    float* As = sm;            // 24960
    float* Bs = As + 24960;    // 24576

    const int tid = threadIdx.x;
    const int tx = tid & 15;
    const int ty = tid >> 4;
    const int n0 = blockIdx.x * 128;

    // gather node_in^T = [h | aggr]^T
    {
        int r = tid >> 1, part = tid & 1;
        int n = n0 + r;
        int nc = (n < NN) ? n : (NN - 1);
        const float4* hr = (const float4*)h + (size_t)nc * 16 + part * 8;
#pragma unroll
        for (int q = 0; q < 8; q++) {
            float4 f = hr[q];
            int k0 = part * 32 + q * 4;
            As[(k0 + 0) * LDA + r] = f.x; As[(k0 + 1) * LDA + r] = f.y;
            As[(k0 + 2) * LDA + r] = f.z; As[(k0 + 3) * LDA + r] = f.w;
        }
        const float4* ar = (const float4*)g_aggr + (size_t)nc * 32 + part * 16;
#pragma unroll
        for (int q = 0; q < 16; q++) {
            float4 f = ar[q];
            int k0 = 64 + part * 64 + q * 4;
            As[(k0 + 0) * LDA + r] = f.x; As[(k0 + 1) * LDA + r] = f.y;
            As[(k0 + 2) * LDA + r] = f.z; As[(k0 + 3) * LDA + r] = f.w;
        }
    }
    for (int i4 = tid; i4 < (192 * 128) / 4; i4 += 256)
        ((float4*)Bs)[i4] = ((const float4*)Wn1)[i4];
    __syncthreads();

    unsigned long long acc[8][4];
    gemm128(As, Bs, bn1, 192, ty, tx, acc);
    __syncthreads();
    store_T(As, acc, ty, tx, true);   // silu, transposed
    for (int i4 = tid; i4 < (128 * 64) / 4; i4 += 256)
        ((float4*)Bs)[i4] = ((const float4*)Wn2)[i4];
    __syncthreads();

    // GEMM2: 128xK(128) * 128x64, LDB = 64
    unsigned long long a2b[8][2];
    {
        const int c0 = tx * 2;
#pragma unroll
        for (int i = 0; i < 2; i++) {
            unsigned long long bi = pk2(bn2[i * 32 + c0], bn2[i * 32 + c0 + 1]);
#pragma unroll
            for (int j = 0; j < 8; j++) a2b[j][i] = bi;
        }
        const float* ap = As + ty * 8;
        const float* bp = Bs + c0;
#pragma unroll 2
        for (int k = 0; k < 128; k++) {
            float2 aA = *(const float2*)(ap + k * LDA + 0);
            float2 aB = *(const float2*)(ap + k * LDA + 2);
            float2 aC = *(const float2*)(ap + k * LDA + 4);
            float2 aD = *(const float2*)(ap + k * LDA + 6);
            unsigned long long a2[8];
            a2[0] = pk2(aA.x, aA.x); a2[1] = pk2(aA.y, aA.y);
            a2[2] = pk2(aB.x, aB.x); a2[3] = pk2(aB.y, aB.y);
            a2[4] = pk2(aC.x, aC.x); a2[5] = pk2(aC.y, aC.y);
            a2[6] = pk2(aD.x, aD.x); a2[7] = pk2(aD.y, aD.y);
            unsigned long long b0 = *(const unsigned long long*)(bp + k * 64 + 0);
            unsigned long long b1 = *(const unsigned long long*)(bp + k * 64 + 32);
#pragma unroll
            for (int j = 0; j < 8; j++) {
                f2fma(a2b[j][0], a2[j], b0);
                f2fma(a2b[j][1], a2[j], b1);
            }
        }
    }
    // residual + store h_new
#pragma unroll
    for (int j = 0; j < 8; j++) {
        int n = n0 + ty * 8 + j;
        if (n < NN) {
#pragma unroll
            for (int i = 0; i < 2; i++) {
                int c = i * 32 + tx * 2;
                float2 hv = *(const float2*)(h + (size_t)n * 64 + c);
                float2 t = up2(a2b[j][i]);
                float2 o; o.x = hv.x + t.x; o.y = hv.y + t.y;
                *(float2*)(out + (size_t)n * 64 + c) = o;
            }
        }
    }
}

// ---------------- launch ----------------

extern "C" void kernel_launch(void* const* d_in, const int* in_sizes, int n_in,
                              void* d_out, int out_size) {
    const float* h   = (const float*)d_in[0];
    const float* x   = (const float*)d_in[1];
    const float* v   = (const float*)d_in[2];
    const int*   ei  = (const int*)d_in[3];      // int32 (JAX x64-disabled demotes int64)
    const float* ea  = (const float*)d_in[4];
    const float* Wm1 = (const float*)d_in[5];
    const float* bm1 = (const float*)d_in[6];
    const float* Wm2 = (const float*)d_in[7];
    const float* bm2 = (const float*)d_in[8];
    const float* Wn1 = (const float*)d_in[9];
    const float* bn1 = (const float*)d_in[10];
    const float* Wn2 = (const float*)d_in[11];
    const float* bn2 = (const float*)d_in[12];
    const float* Wc1 = (const float*)d_in[13];
    const float* bc1 = (const float*)d_in[14];
    const float* Wc2 = (const float*)d_in[15];
    const float* bc2 = (const float*)d_in[16];
    const float* Wv1 = (const float*)d_in[17];
    const float* bv1 = (const float*)d_in[18];
    const float* Wv2 = (const float*)d_in[19];
    const float* bv2 = (const float*)d_in[20];
    float* out = (float*)d_out;

    cudaFuncSetAttribute(edge_kernel, cudaFuncAttributeMaxDynamicSharedMemorySize, EDGE_SMEM_BYTES);
    cudaFuncSetAttribute(node_kernel, cudaFuncAttributeMaxDynamicSharedMemorySize, NODE_SMEM_BYTES);

    init_kernel<<<2048, 256>>>(x, v, out);
    edge_kernel<<<EE / 128, 256, EDGE_SMEM_BYTES>>>(
        h, x, ei, ea, Wm1, bm1, Wm2, bm2, Wc1, bc1, Wc2, bc2, Wv1, bv1, Wv2, bv2,
        out + (size_t)NN * ND, out + (size_t)NN * ND + (size_t)NN * 3);
    node_kernel<<<(NN + 127) / 128, 256, NODE_SMEM_BYTES>>>(h, Wn1, bn1, Wn2, bn2, out);
}